// round 6
// baseline (speedup 1.0000x reference)
#include <cuda_runtime.h>
#include <cuda_bf16.h>
#include <cstdint>

#define B_SZ 1024
#define FIN  4096
#define NMEM 256
#define SQF  64
#define QKN  16384
typedef __nv_bfloat16 bf16;

#define XMAX 5.5f
#define WMAX 0.1f
#define QSCALE ((XMAX / 127.f) * (WMAX / 127.f))

// scratch
__device__ float g_tmp[B_SZ * QKN];
__device__ float g_qsum[B_SZ * SQF];
__device__ bf16 g_savgh[B_SZ * NMEM], g_savgl[B_SZ * NMEM];
__device__ bf16 g_ph[B_SZ * FIN], g_pl[B_SZ * FIN];
__device__ bf16 g_vh[NMEM * FIN], g_vl[NMEM * FIN];
__device__ bf16 g_wlh[FIN * FIN], g_wll[FIN * FIN];
__device__ int8_t g_x1[B_SZ * FIN], g_x2[B_SZ * FIN];
__device__ int8_t g_wq1[(size_t)QKN * FIN], g_wq2[(size_t)QKN * FIN];  // [N,K]
__device__ int8_t g_wk1[(size_t)QKN * FIN], g_wk2[(size_t)QKN * FIN];  // [N,K]

__device__ __forceinline__ uint32_t smem_u32(const void* p) {
    uint32_t a;
    asm("{ .reg .u64 t; cvta.to.shared.u64 t, %1; cvt.u32.u64 %0, t; }"
        : "=r"(a) : "l"(p));
    return a;
}
__device__ __forceinline__ void ldsm4(uint32_t* r, uint32_t a) {
    asm volatile("ldmatrix.sync.aligned.m8n8.x4.shared.b16 {%0,%1,%2,%3}, [%4];"
                 : "=r"(r[0]), "=r"(r[1]), "=r"(r[2]), "=r"(r[3]) : "r"(a));
}
__device__ __forceinline__ void ldsm4t(uint32_t* r, uint32_t a) {
    asm volatile("ldmatrix.sync.aligned.m8n8.x4.trans.shared.b16 {%0,%1,%2,%3}, [%4];"
                 : "=r"(r[0]), "=r"(r[1]), "=r"(r[2]), "=r"(r[3]) : "r"(a));
}
__device__ __forceinline__ void mma_bf16(float* d, const uint32_t* a, const uint32_t* b) {
    asm volatile(
        "mma.sync.aligned.m16n8k16.row.col.f32.bf16.bf16.f32 "
        "{%0,%1,%2,%3}, {%4,%5,%6,%7}, {%8,%9}, {%0,%1,%2,%3};"
        : "+f"(d[0]), "+f"(d[1]), "+f"(d[2]), "+f"(d[3])
        : "r"(a[0]), "r"(a[1]), "r"(a[2]), "r"(a[3]), "r"(b[0]), "r"(b[1]));
}
__device__ __forceinline__ void imma(int* d, const uint32_t* a, uint32_t b0, uint32_t b1) {
    asm volatile(
        "mma.sync.aligned.m16n8k32.row.col.s32.s8.s8.s32 "
        "{%0,%1,%2,%3}, {%4,%5,%6,%7}, {%8,%9}, {%0,%1,%2,%3};"
        : "+r"(d[0]), "+r"(d[1]), "+r"(d[2]), "+r"(d[3])
        : "r"(a[0]), "r"(a[1]), "r"(a[2]), "r"(a[3]), "r"(b0), "r"(b1));
}
__device__ __forceinline__ void cpa16(uint32_t dst, const void* src) {
    asm volatile("cp.async.ca.shared.global [%0], [%1], 16;" :: "r"(dst), "l"(src));
}
__device__ __forceinline__ void cpa_commit() {
    asm volatile("cp.async.commit_group;" ::: "memory");
}
template<int N> __device__ __forceinline__ void cpa_wait() {
    asm volatile("cp.async.wait_group %0;" :: "n"(N) : "memory");
}
__device__ __forceinline__ void split2(float x, float y, uint32_t& hi, uint32_t& lo) {
    bf16 hx = __float2bfloat16(x);
    bf16 hy = __float2bfloat16(y);
    bf16 lx = __float2bfloat16(x - __bfloat162float(hx));
    bf16 ly = __float2bfloat16(y - __bfloat162float(hy));
    hi = (uint32_t)__bfloat16_as_ushort(hx) | ((uint32_t)__bfloat16_as_ushort(hy) << 16);
    lo = (uint32_t)__bfloat16_as_ushort(lx) | ((uint32_t)__bfloat16_as_ushort(ly) << 16);
}
__device__ __forceinline__ void q2dig(float v, float s, char& a, char& b) {
    int q = __float2int_rn(v * s);
    q = q > 127 ? 127 : (q < -127 ? -127 : q);
    float r = v * s - (float)q;
    int q2 = __float2int_rn(r * 256.f);
    q2 = q2 > 127 ? 127 : (q2 < -127 ? -127 : q2);
    a = (char)q; b = (char)q2;
}

// ---------------------------------------------------------------------------
// fp32 -> bf16 hi/lo (for Wl, v)
// ---------------------------------------------------------------------------
__global__ void conv_kernel(const float4* __restrict__ in,
                            uint2* __restrict__ hi, uint2* __restrict__ lo, int n4)
{
    int i = blockIdx.x * blockDim.x + threadIdx.x;
    const int stride = gridDim.x * blockDim.x;
    for (; i < n4; i += stride) {
        float4 v = in[i];
        uint32_t h0, l0, h1, l1;
        split2(v.x, v.y, h0, l0);
        split2(v.z, v.w, h1, l1);
        hi[i] = make_uint2(h0, h1);
        lo[i] = make_uint2(l0, l1);
    }
}

// ---------------------------------------------------------------------------
// x fp32 [M,K] -> 2-digit int8, same layout
// ---------------------------------------------------------------------------
__global__ void quant_x(const float4* __restrict__ in,
                        char4* __restrict__ q1, char4* __restrict__ q2, int n4)
{
    int i = blockIdx.x * blockDim.x + threadIdx.x;
    const int stride = gridDim.x * blockDim.x;
    const float s = 127.f / XMAX;
    for (; i < n4; i += stride) {
        float4 v = in[i];
        char a0,b0,a1,b1,a2,b2,a3,b3;
        q2dig(v.x, s, a0, b0); q2dig(v.y, s, a1, b1);
        q2dig(v.z, s, a2, b2); q2dig(v.w, s, a3, b3);
        q1[i] = make_char4(a0, a1, a2, a3);
        q2[i] = make_char4(b0, b1, b2, b3);
    }
}

// ---------------------------------------------------------------------------
// W fp32 [K,N] -> transposed 2-digit int8 [N,K]
// ---------------------------------------------------------------------------
__global__ void quant_wT(const float* __restrict__ W,
                         int8_t* __restrict__ q1, int8_t* __restrict__ q2,
                         int N, int K)
{
    __shared__ float s[64][65];
    const int t = threadIdx.x;
    const int n0 = blockIdx.x * 64, k0 = blockIdx.y * 64;
    #pragma unroll
    for (int it = 0; it < 16; it++) {
        int kk = (t >> 6) + it * 4, nn = t & 63;
        s[kk][nn] = W[(size_t)(k0 + kk) * N + n0 + nn];
    }
    __syncthreads();
    const int nr = t >> 2, ks = (t & 3) * 16;
    const float sc = 127.f / WMAX;
    __align__(16) char o1[16];
    __align__(16) char o2[16];
    #pragma unroll
    for (int i = 0; i < 16; i++) {
        char a, b;
        q2dig(s[ks + i][nr], sc, a, b);
        o1[i] = a; o2[i] = b;
    }
    *(uint4*)&q1[(size_t)(n0 + nr) * K + k0 + ks] = *(uint4*)o1;
    *(uint4*)&q2[(size_t)(n0 + nr) * K + k0 + ks] = *(uint4*)o2;
}

// ---------------------------------------------------------------------------
// int8 2-digit GEMM: C = scale*(Ahh*Bhh + cross/256) (+bias)(relu)
// A [M,K] row-major int8 x2; B [N,K] row-major (i.e. col-major for mma) x2.
// CTA 128x128, BK=64, 3-stage cp.async. warp tile 64x32.
// ---------------------------------------------------------------------------
#define ISTAGE 32768

template<bool RELU, bool BIAS>
__global__ __launch_bounds__(256, 1)
void igemm(const int8_t* __restrict__ A1, const int8_t* __restrict__ A2,
           const int8_t* __restrict__ B1, const int8_t* __restrict__ B2,
           const float* __restrict__ bias, float* __restrict__ C,
           int M, int N, int K, float scale)
{
    extern __shared__ uint8_t smem[];
    const uint32_t sb = smem_u32(smem);
    const int tid = threadIdx.x, lane = tid & 31, wid = tid >> 5;
    const int wm = wid & 1, wn = wid >> 1;
    const int bm0 = blockIdx.x * 128, bn0 = blockIdx.y * 128;

    const int lr = tid >> 2, lseg = (tid & 3) * 16;
    const int NC = K >> 6;

    auto issue = [&](int c) {
        const uint32_t u = sb + (uint32_t)(c % 3) * ISTAGE;
        const int8_t* pa1 = A1 + (size_t)bm0 * K + (size_t)c * 64;
        const int8_t* pa2 = A2 + (size_t)bm0 * K + (size_t)c * 64;
        const int8_t* pb1 = B1 + (size_t)bn0 * K + (size_t)c * 64;
        const int8_t* pb2 = B2 + (size_t)bn0 * K + (size_t)c * 64;
        #pragma unroll
        for (int h = 0; h < 2; h++) {
            int row = lr + 64 * h;
            uint32_t off = (uint32_t)(row * 64 + lseg);
            uint32_t sw = off ^ ((uint32_t)(row & 3) << 4);
            const size_t g = (size_t)row * K + lseg;
            cpa16(u + sw,         pa1 + g);
            cpa16(u + 8192 + sw,  pa2 + g);
            cpa16(u + 16384 + sw, pb1 + g);
            cpa16(u + 24576 + sw, pb2 + g);
        }
        cpa_commit();
    };

    int hh[16][4], cr[16][4];
    #pragma unroll
    for (int i = 0; i < 16; i++)
        #pragma unroll
        for (int j = 0; j < 4; j++) { hh[i][j] = 0; cr[i][j] = 0; }

    issue(0); issue(1); issue(2);

    for (int c = 0; c < NC; c++) {
        cpa_wait<2>();
        __syncthreads();
        const uint32_t u = sb + (uint32_t)(c % 3) * ISTAGE;
        #pragma unroll
        for (int ks = 0; ks < 2; ks++) {
            uint32_t a1f[4][4], a2f[4][4], b1f[2][4], b2f[2][4];
            #pragma unroll
            for (int mi = 0; mi < 4; mi++) {
                int row = wm * 64 + mi * 16 + (lane & 15);
                uint32_t off = (uint32_t)(row * 64 + ks * 32 + (lane >> 4) * 16);
                uint32_t sw = off ^ ((uint32_t)(row & 3) << 4);
                ldsm4(a1f[mi], u + sw);
                ldsm4(a2f[mi], u + 8192 + sw);
            }
            #pragma unroll
            for (int jp = 0; jp < 2; jp++) {
                int row = wn * 32 + jp * 16 + (lane & 15);
                uint32_t off = (uint32_t)(row * 64 + ks * 32 + (lane >> 4) * 16);
                uint32_t sw = off ^ ((uint32_t)(row & 3) << 4);
                ldsm4(b1f[jp], u + 16384 + sw);
                ldsm4(b2f[jp], u + 24576 + sw);
            }
            #pragma unroll
            for (int mi = 0; mi < 4; mi++)
                #pragma unroll
                for (int nj = 0; nj < 4; nj++) {
                    const int jp = nj >> 1, h = nj & 1;
                    imma(hh[mi * 4 + nj], a1f[mi], b1f[jp][h], b1f[jp][h + 2]);
                    imma(cr[mi * 4 + nj], a1f[mi], b2f[jp][h], b2f[jp][h + 2]);
                    imma(cr[mi * 4 + nj], a2f[mi], b1f[jp][h], b1f[jp][h + 2]);
                }
        }
        __syncthreads();
        if (c + 3 < NC) issue(c + 3);
    }

    #pragma unroll
    for (int mi = 0; mi < 4; mi++) {
        const int r0 = bm0 + wm * 64 + mi * 16 + (lane >> 2);
        #pragma unroll
        for (int nj = 0; nj < 4; nj++) {
            const int col = bn0 + wn * 32 + nj * 8 + (lane & 3) * 2;
            const int* dh = hh[mi * 4 + nj];
            const int* dc = cr[mi * 4 + nj];
            float v[4];
            #pragma unroll
            for (int q = 0; q < 4; q++)
                v[q] = scale * ((float)dh[q] + 0.00390625f * (float)dc[q]);
            if (BIAS) {
                float2 bb = *(const float2*)&bias[col];
                v[0] += bb.x; v[1] += bb.y; v[2] += bb.x; v[3] += bb.y;
            }
            if (RELU) {
                v[0] = fmaxf(v[0], 0.f); v[1] = fmaxf(v[1], 0.f);
                v[2] = fmaxf(v[2], 0.f); v[3] = fmaxf(v[3], 0.f);
            }
            *(float2*)&C[(size_t)r0 * N + col] = make_float2(v[0], v[1]);
            *(float2*)&C[(size_t)(r0 + 8) * N + col] = make_float2(v[2], v[3]);
        }
    }
}

// ---------------------------------------------------------------------------
// bf16 split-3 GEMM (for GEMM5/6) — unchanged from R4
// ---------------------------------------------------------------------------
#define STAGE_B 32768

template<bool RELU, bool BIAS, bool RES, bool OUTBF>
__global__ __launch_bounds__(256)
void tgemm(const bf16* __restrict__ Ah, const bf16* __restrict__ Al,
           const bf16* __restrict__ Bh, const bf16* __restrict__ Bl,
           const float* __restrict__ bias, const float* __restrict__ res,
           float* __restrict__ C, bf16* __restrict__ Ch, bf16* __restrict__ Cl,
           int M, int N, int K)
{
    extern __shared__ uint8_t smem[];
    const uint32_t sb = smem_u32(smem);
    const int tid = threadIdx.x;
    const int lane = tid & 31, wid = tid >> 5;
    const int wm = wid & 1, wn = wid >> 1;
    const int bm0 = blockIdx.x * 128, bn0 = blockIdx.y * 128;

    const int arow = tid >> 1, ac = (tid & 1) * 32;
    const int brow = tid >> 3, bc = (tid & 7) * 32;
    const bf16* pAh = Ah + (size_t)(bm0 + arow) * K + ac / 2;
    const bf16* pAl = Al + (size_t)(bm0 + arow) * K + ac / 2;
    const bf16* pBh = Bh + (size_t)brow * N + bn0 + bc / 2;
    const bf16* pBl = Bl + (size_t)brow * N + bn0 + bc / 2;
    const uint32_t aswz = (uint32_t)((arow & 3) << 4);
    const uint32_t bswz = (uint32_t)((brow & 7) << 4);
    const uint32_t ao = (uint32_t)(arow * 64 + ac);
    const uint32_t bo = (uint32_t)(brow * 256 + bc);

    const int NC = K >> 5;

    auto issue = [&](int c) {
        const uint32_t u = sb + (uint32_t)(c % 3) * STAGE_B;
        const bf16* sAh = pAh + c * 32;
        const bf16* sAl = pAl + c * 32;
        const bf16* sBh = pBh + (size_t)c * 32 * N;
        const bf16* sBl = pBl + (size_t)c * 32 * N;
        cpa16(u + ((ao) ^ aswz), sAh);
        cpa16(u + ((ao + 16) ^ aswz), sAh + 8);
        cpa16(u + 8192 + ((ao) ^ aswz), sAl);
        cpa16(u + 8192 + ((ao + 16) ^ aswz), sAl + 8);
        cpa16(u + 16384 + ((bo) ^ bswz), sBh);
        cpa16(u + 16384 + ((bo + 16) ^ bswz), sBh + 8);
        cpa16(u + 24576 + ((bo) ^ bswz), sBl);
        cpa16(u + 24576 + ((bo + 16) ^ bswz), sBl + 8);
        cpa_commit();
    };

    float acc[16][4];
    #pragma unroll
    for (int i = 0; i < 16; i++)
        #pragma unroll
        for (int j = 0; j < 4; j++) acc[i][j] = 0.f;

    issue(0); issue(1); issue(2);

    for (int c = 0; c < NC; c++) {
        cpa_wait<2>();
        __syncthreads();
        const uint32_t u = sb + (uint32_t)(c % 3) * STAGE_B;
        #pragma unroll
        for (int ks = 0; ks < 2; ks++) {
            uint32_t ah[4][4], al[4][4], bh[2][4], bl[2][4];
            #pragma unroll
            for (int mi = 0; mi < 4; mi++) {
                int row = wm * 64 + mi * 16 + (lane & 15);
                uint32_t ad = (uint32_t)(row * 64 + ks * 32 + (lane >> 4) * 16);
                uint32_t sw = ad ^ ((uint32_t)(row & 3) << 4);
                ldsm4(ah[mi], u + sw);
                ldsm4(al[mi], u + 8192 + sw);
            }
            #pragma unroll
            for (int j = 0; j < 2; j++) {
                int kk = ks * 16 + (lane & 15);
                int nn = wn * 32 + j * 16 + (lane >> 4) * 8;
                uint32_t bd = (uint32_t)(kk * 256 + nn * 2);
                uint32_t sw = bd ^ ((uint32_t)(kk & 7) << 4);
                ldsm4t(bh[j], u + 16384 + sw);
                ldsm4t(bl[j], u + 24576 + sw);
            }
            #pragma unroll
            for (int mi = 0; mi < 4; mi++)
                #pragma unroll
                for (int nj = 0; nj < 4; nj++) {
                    const uint32_t* Bh2 = &bh[nj >> 1][(nj & 1) * 2];
                    const uint32_t* Bl2 = &bl[nj >> 1][(nj & 1) * 2];
                    float* d = acc[mi * 4 + nj];
                    mma_bf16(d, ah[mi], Bh2);
                    mma_bf16(d, ah[mi], Bl2);
                    mma_bf16(d, al[mi], Bh2);
                }
        }
        __syncthreads();
        if (c + 3 < NC) issue(c + 3);
    }

    #pragma unroll
    for (int mi = 0; mi < 4; mi++) {
        const int r0 = bm0 + wm * 64 + mi * 16 + (lane >> 2);
        #pragma unroll
        for (int nj = 0; nj < 4; nj++) {
            const int col = bn0 + wn * 32 + nj * 8 + (lane & 3) * 2;
            float* d = acc[mi * 4 + nj];
            if (OUTBF) {
                #pragma unroll
                for (int h = 0; h < 2; h++) {
                    const int rr = r0 + 8 * h;
                    uint32_t hi, lo;
                    split2(d[2 * h], d[2 * h + 1], hi, lo);
                    *(uint32_t*)&Ch[(size_t)rr * N + col] = hi;
                    *(uint32_t*)&Cl[(size_t)rr * N + col] = lo;
                }
            } else {
                float2 o0 = make_float2(d[0], d[1]);
                float2 o1 = make_float2(d[2], d[3]);
                if (BIAS) {
                    float2 bb = *(const float2*)&bias[col];
                    o0.x += bb.x; o0.y += bb.y; o1.x += bb.x; o1.y += bb.y;
                }
                if (RES) {
                    float2 s0 = *(const float2*)&res[(size_t)r0 * N + col];
                    float2 s1 = *(const float2*)&res[(size_t)(r0 + 8) * N + col];
                    o0.x += s0.x; o0.y += s0.y; o1.x += s1.x; o1.y += s1.y;
                }
                if (RELU) {
                    o0.x = fmaxf(o0.x, 0.f); o0.y = fmaxf(o0.y, 0.f);
                    o1.x = fmaxf(o1.x, 0.f); o1.y = fmaxf(o1.y, 0.f);
                }
                *(float2*)&C[(size_t)r0 * N + col] = o0;
                *(float2*)&C[(size_t)(r0 + 8) * N + col] = o1;
            }
        }
    }
}

__global__ void qsum_kernel()
{
    const int b = blockIdx.x, t = threadIdx.x;
    const int s = t & 63, g = t >> 6;
    const float* base = g_tmp + (size_t)b * QKN;
    float sum = 0.f;
    #pragma unroll 4
    for (int m = g; m < NMEM; m += 4) sum += base[m * SQF + s];
    __shared__ float sh[4][64];
    sh[g][s] = sum;
    __syncthreads();
    if (g == 0)
        g_qsum[b * SQF + s] = sh[0][s] + sh[1][s] + sh[2][s] + sh[3][s];
}

__global__ void savg_kernel()
{
    const int b = blockIdx.x, t = threadIdx.x;
    const int lane = t & 31, w = t >> 5;
    __shared__ float q[64];
    if (t < 64) q[t] = g_qsum[b * SQF + t];
    __syncthreads();
    const float* base = g_tmp + (size_t)b * QKN;
    const float inv = 1.0f / (256.0f * 8.0f);
    for (int n = w; n < NMEM; n += 8) {
        float sum = base[n * SQF + lane] * q[lane]
                  + base[n * SQF + 32 + lane] * q[32 + lane];
        #pragma unroll
        for (int off = 16; off; off >>= 1)
            sum += __shfl_xor_sync(0xffffffffu, sum, off);
        if (lane == 0) {
            float val = sum * inv;
            bf16 h = __float2bfloat16(val);
            bf16 l = __float2bfloat16(val - __bfloat162float(h));
            g_savgh[b * NMEM + n] = h;
            g_savgl[b * NMEM + n] = l;
        }
    }
}

extern "C" void kernel_launch(void* const* d_in, const int* in_sizes, int n_in,
                              void* d_out, int out_size)
{
    const float* x  = (const float*)d_in[0];
    const float* Wq = (const float*)d_in[1];
    const float* bq = (const float*)d_in[2];
    const float* Wk = (const float*)d_in[3];
    const float* bk = (const float*)d_in[4];
    const float* v  = (const float*)d_in[5];
    const float* Wl = (const float*)d_in[6];
    const float* bl = (const float*)d_in[7];
    float* out = (float*)d_out;

    float* tmp;
    cudaGetSymbolAddress((void**)&tmp, g_tmp);
    bf16 *wlh,*wll,*vh,*vl,*sh,*sl,*ph,*pl;
    cudaGetSymbolAddress((void**)&wlh, g_wlh); cudaGetSymbolAddress((void**)&wll, g_wll);
    cudaGetSymbolAddress((void**)&vh, g_vh);   cudaGetSymbolAddress((void**)&vl, g_vl);
    cudaGetSymbolAddress((void**)&sh, g_savgh);cudaGetSymbolAddress((void**)&sl, g_savgl);
    cudaGetSymbolAddress((void**)&ph, g_ph);   cudaGetSymbolAddress((void**)&pl, g_pl);
    int8_t *x1,*x2,*wq1,*wq2,*wk1,*wk2;
    cudaGetSymbolAddress((void**)&x1, g_x1);   cudaGetSymbolAddress((void**)&x2, g_x2);
    cudaGetSymbolAddress((void**)&wq1, g_wq1); cudaGetSymbolAddress((void**)&wq2, g_wq2);
    cudaGetSymbolAddress((void**)&wk1, g_wk1); cudaGetSymbolAddress((void**)&wk2, g_wk2);

    // quantize / convert
    quant_x<<<512, 256>>>((const float4*)x, (char4*)x1, (char4*)x2, B_SZ * FIN / 4);
    quant_wT<<<dim3(QKN / 64, FIN / 64), 256>>>(Wq, wq1, wq2, QKN, FIN);
    quant_wT<<<dim3(QKN / 64, FIN / 64), 256>>>(Wk, wk1, wk2, QKN, FIN);
    conv_kernel<<<2048, 256>>>((const float4*)Wl, (uint2*)wlh, (uint2*)wll, FIN * FIN / 4);
    conv_kernel<<<512,  256>>>((const float4*)v,  (uint2*)vh,  (uint2*)vl,  NMEM * FIN / 4);

    const int ISM = 3 * ISTAGE;
    const int SM = 3 * STAGE_B;
    cudaFuncSetAttribute(igemm<true, true>,
                         cudaFuncAttributeMaxDynamicSharedMemorySize, ISM);
    cudaFuncSetAttribute(tgemm<false, false, false, true>,
                         cudaFuncAttributeMaxDynamicSharedMemorySize, SM);
    cudaFuncSetAttribute(tgemm<false, true, true, false>,
                         cudaFuncAttributeMaxDynamicSharedMemorySize, SM);

    {   // 1) relu(x@Wq+bq) -> tmp   (int8 path)
        dim3 g(B_SZ / 128, QKN / 128);
        igemm<true, true><<<g, 256, ISM>>>(x1, x2, wq1, wq2, bq, tmp,
                                           B_SZ, QKN, FIN, QSCALE);
    }
    qsum_kernel<<<B_SZ, 256>>>();
    {   // 2) relu(x@Wk+bk) -> tmp   (int8 path)
        dim3 g(B_SZ / 128, QKN / 128);
        igemm<true, true><<<g, 256, ISM>>>(x1, x2, wk1, wk2, bk, tmp,
                                           B_SZ, QKN, FIN, QSCALE);
    }
    savg_kernel<<<B_SZ, 256>>>();
    {   // 3) pooled = s_avg @ v  (bf16, hi/lo out)
        dim3 g(B_SZ / 128, FIN / 128);
        tgemm<false, false, false, true><<<g, 256, SM>>>(
            sh, sl, vh, vl, nullptr, nullptr, nullptr, ph, pl, B_SZ, FIN, NMEM);
    }
    {   // 4) out = x + pooled@Wl + bl  (bf16)
        dim3 g(B_SZ / 128, FIN / 128);
        tgemm<false, true, true, false><<<g, 256, SM>>>(
            ph, pl, wlh, wll, bl, x, out, nullptr, nullptr, B_SZ, FIN, FIN);
    }
}

// round 8
// speedup vs baseline: 3.5996x; 3.5996x over previous
#include <cuda_runtime.h>
#include <cuda_bf16.h>
#include <cstdint>

#define B_SZ 1024
#define FIN  4096
#define NMEM 256
#define SQF  64
#define QKN  16384
typedef __nv_bfloat16 bf16;

// scratch
__device__ float g_tmp[B_SZ * QKN];      // relu(xq) then relu(xk)
__device__ float g_qsum[B_SZ * SQF];
__device__ bf16 g_savgh[B_SZ * NMEM], g_savgl[B_SZ * NMEM];
__device__ bf16 g_ph[B_SZ * FIN], g_pl[B_SZ * FIN];
__device__ bf16 g_vh[NMEM * FIN], g_vl[NMEM * FIN];
__device__ bf16 g_wlh[FIN * FIN], g_wll[FIN * FIN];
__device__ bf16 g_xh[B_SZ * FIN];
__device__ bf16 g_wqh[(size_t)FIN * QKN];
__device__ bf16 g_wkh[(size_t)FIN * QKN];

__device__ __forceinline__ uint32_t smem_u32(const void* p) {
    uint32_t a;
    asm("{ .reg .u64 t; cvta.to.shared.u64 t, %1; cvt.u32.u64 %0, t; }"
        : "=r"(a) : "l"(p));
    return a;
}
__device__ __forceinline__ void ldsm4(uint32_t* r, uint32_t a) {
    asm volatile("ldmatrix.sync.aligned.m8n8.x4.shared.b16 {%0,%1,%2,%3}, [%4];"
                 : "=r"(r[0]), "=r"(r[1]), "=r"(r[2]), "=r"(r[3]) : "r"(a));
}
__device__ __forceinline__ void ldsm4t(uint32_t* r, uint32_t a) {
    asm volatile("ldmatrix.sync.aligned.m8n8.x4.trans.shared.b16 {%0,%1,%2,%3}, [%4];"
                 : "=r"(r[0]), "=r"(r[1]), "=r"(r[2]), "=r"(r[3]) : "r"(a));
}
__device__ __forceinline__ void mma_bf16(float* d, const uint32_t* a, const uint32_t* b) {
    asm volatile(
        "mma.sync.aligned.m16n8k16.row.col.f32.bf16.bf16.f32 "
        "{%0,%1,%2,%3}, {%4,%5,%6,%7}, {%8,%9}, {%0,%1,%2,%3};"
        : "+f"(d[0]), "+f"(d[1]), "+f"(d[2]), "+f"(d[3])
        : "r"(a[0]), "r"(a[1]), "r"(a[2]), "r"(a[3]), "r"(b[0]), "r"(b[1]));
}
__device__ __forceinline__ void cpa16(uint32_t dst, const void* src) {
    asm volatile("cp.async.ca.shared.global [%0], [%1], 16;" :: "r"(dst), "l"(src));
}
__device__ __forceinline__ void cpa_commit() {
    asm volatile("cp.async.commit_group;" ::: "memory");
}
template<int N> __device__ __forceinline__ void cpa_wait() {
    asm volatile("cp.async.wait_group %0;" :: "n"(N) : "memory");
}
__device__ __forceinline__ void split2(float x, float y, uint32_t& hi, uint32_t& lo) {
    bf16 hx = __float2bfloat16(x);
    bf16 hy = __float2bfloat16(y);
    bf16 lx = __float2bfloat16(x - __bfloat162float(hx));
    bf16 ly = __float2bfloat16(y - __bfloat162float(hy));
    hi = (uint32_t)__bfloat16_as_ushort(hx) | ((uint32_t)__bfloat16_as_ushort(hy) << 16);
    lo = (uint32_t)__bfloat16_as_ushort(lx) | ((uint32_t)__bfloat16_as_ushort(ly) << 16);
}

// fp32 -> bf16 hi/lo
__global__ void conv_kernel(const float4* __restrict__ in,
                            uint2* __restrict__ hi, uint2* __restrict__ lo, int n4)
{
    int i = blockIdx.x * blockDim.x + threadIdx.x;
    const int stride = gridDim.x * blockDim.x;
    for (; i < n4; i += stride) {
        float4 v = in[i];
        uint32_t h0, l0, h1, l1;
        split2(v.x, v.y, h0, l0);
        split2(v.z, v.w, h1, l1);
        hi[i] = make_uint2(h0, h1);
        lo[i] = make_uint2(l0, l1);
    }
}

// fp32 -> bf16 (round only)
__global__ void conv1_kernel(const float4* __restrict__ in,
                             uint2* __restrict__ hi, int n4)
{
    int i = blockIdx.x * blockDim.x + threadIdx.x;
    const int stride = gridDim.x * blockDim.x;
    for (; i < n4; i += stride) {
        float4 v = in[i];
        uint32_t h0 = (uint32_t)__bfloat16_as_ushort(__float2bfloat16(v.x))
                    | ((uint32_t)__bfloat16_as_ushort(__float2bfloat16(v.y)) << 16);
        uint32_t h1 = (uint32_t)__bfloat16_as_ushort(__float2bfloat16(v.z))
                    | ((uint32_t)__bfloat16_as_ushort(__float2bfloat16(v.w)) << 16);
        hi[i] = make_uint2(h0, h1);
    }
}

// ---------------------------------------------------------------------------
// bf16 GEMM, TERMS=1 (plain) or 3 (hi/lo split). CTA 128x128, BK=32,
// 3-stage cp.async. stage: Ah[0,8K) Al[8K,16K) Bh[16K,24K) Bl[24K,32K)
// ---------------------------------------------------------------------------
#define STAGE_B 32768

template<int TERMS, bool RELU, bool BIAS, bool RES, bool OUTBF>
__global__ __launch_bounds__(256)
void tgemm(const bf16* __restrict__ Ah, const bf16* __restrict__ Al,
           const bf16* __restrict__ Bh, const bf16* __restrict__ Bl,
           const float* __restrict__ bias, const float* __restrict__ res,
           float* __restrict__ C, bf16* __restrict__ Ch, bf16* __restrict__ Cl,
           int M, int N, int K)
{
    extern __shared__ uint8_t smem[];
    const uint32_t sb = smem_u32(smem);
    const int tid = threadIdx.x;
    const int lane = tid & 31, wid = tid >> 5;
    const int wm = wid & 1, wn = wid >> 1;
    const int bm0 = blockIdx.x * 128, bn0 = blockIdx.y * 128;

    const int arow = tid >> 1, ac = (tid & 1) * 32;
    const int brow = tid >> 3, bc = (tid & 7) * 32;
    const bf16* pAh = Ah + (size_t)(bm0 + arow) * K + ac / 2;
    const bf16* pAl = (TERMS == 3) ? Al + (size_t)(bm0 + arow) * K + ac / 2 : nullptr;
    const bf16* pBh = Bh + (size_t)brow * N + bn0 + bc / 2;
    const bf16* pBl = (TERMS == 3) ? Bl + (size_t)brow * N + bn0 + bc / 2 : nullptr;
    const uint32_t aswz = (uint32_t)((arow & 3) << 4);
    const uint32_t bswz = (uint32_t)((brow & 7) << 4);
    const uint32_t ao = (uint32_t)(arow * 64 + ac);
    const uint32_t bo = (uint32_t)(brow * 256 + bc);

    const int NC = K >> 5;

    auto issue = [&](int c) {
        const uint32_t u = sb + (uint32_t)(c % 3) * STAGE_B;
        const bf16* sAh = pAh + c * 32;
        const bf16* sBh = pBh + (size_t)c * 32 * N;
        cpa16(u + ((ao) ^ aswz), sAh);
        cpa16(u + ((ao + 16) ^ aswz), sAh + 8);
        cpa16(u + 16384 + ((bo) ^ bswz), sBh);
        cpa16(u + 16384 + ((bo + 16) ^ bswz), sBh + 8);
        if (TERMS == 3) {
            const bf16* sAl = pAl + c * 32;
            const bf16* sBl = pBl + (size_t)c * 32 * N;
            cpa16(u + 8192 + ((ao) ^ aswz), sAl);
            cpa16(u + 8192 + ((ao + 16) ^ aswz), sAl + 8);
            cpa16(u + 24576 + ((bo) ^ bswz), sBl);
            cpa16(u + 24576 + ((bo + 16) ^ bswz), sBl + 8);
        }
        cpa_commit();
    };

    float acc[16][4];
    #pragma unroll
    for (int i = 0; i < 16; i++)
        #pragma unroll
        for (int j = 0; j < 4; j++) acc[i][j] = 0.f;

    issue(0); issue(1); issue(2);

    for (int c = 0; c < NC; c++) {
        cpa_wait<2>();
        __syncthreads();
        const uint32_t u = sb + (uint32_t)(c % 3) * STAGE_B;
        #pragma unroll
        for (int ks = 0; ks < 2; ks++) {
            uint32_t ah[4][4], al[4][4], bh[2][4], bl[2][4];
            #pragma unroll
            for (int mi = 0; mi < 4; mi++) {
                int row = wm * 64 + mi * 16 + (lane & 15);
                uint32_t ad = (uint32_t)(row * 64 + ks * 32 + (lane >> 4) * 16);
                uint32_t sw = ad ^ ((uint32_t)(row & 3) << 4);
                ldsm4(ah[mi], u + sw);
                if (TERMS == 3) ldsm4(al[mi], u + 8192 + sw);
            }
            #pragma unroll
            for (int j = 0; j < 2; j++) {
                int kk = ks * 16 + (lane & 15);
                int nn = wn * 32 + j * 16 + (lane >> 4) * 8;
                uint32_t bd = (uint32_t)(kk * 256 + nn * 2);
                uint32_t sw = bd ^ ((uint32_t)(kk & 7) << 4);
                ldsm4t(bh[j], u + 16384 + sw);
                if (TERMS == 3) ldsm4t(bl[j], u + 24576 + sw);
            }
            #pragma unroll
            for (int mi = 0; mi < 4; mi++)
                #pragma unroll
                for (int nj = 0; nj < 4; nj++) {
                    const uint32_t* Bh2 = &bh[nj >> 1][(nj & 1) * 2];
                    float* d = acc[mi * 4 + nj];
                    mma_bf16(d, ah[mi], Bh2);
                    if (TERMS == 3) {
                        const uint32_t* Bl2 = &bl[nj >> 1][(nj & 1) * 2];
                        mma_bf16(d, ah[mi], Bl2);
                        mma_bf16(d, al[mi], Bh2);
                    }
                }
        }
        __syncthreads();
        if (c + 3 < NC) issue(c + 3);
    }

    #pragma unroll
    for (int mi = 0; mi < 4; mi++) {
        const int r0 = bm0 + wm * 64 + mi * 16 + (lane >> 2);
        #pragma unroll
        for (int nj = 0; nj < 4; nj++) {
            const int col = bn0 + wn * 32 + nj * 8 + (lane & 3) * 2;
            float* d = acc[mi * 4 + nj];
            if (OUTBF) {
                #pragma unroll
                for (int h = 0; h < 2; h++) {
                    const int rr = r0 + 8 * h;
                    uint32_t hi, lo;
                    split2(d[2 * h], d[2 * h + 1], hi, lo);
                    *(uint32_t*)&Ch[(size_t)rr * N + col] = hi;
                    *(uint32_t*)&Cl[(size_t)rr * N + col] = lo;
                }
            } else {
                float2 o0 = make_float2(d[0], d[1]);
                float2 o1 = make_float2(d[2], d[3]);
                if (BIAS) {
                    float2 bb = *(const float2*)&bias[col];
                    o0.x += bb.x; o0.y += bb.y; o1.x += bb.x; o1.y += bb.y;
                }
                if (RES) {
                    float2 s0 = *(const float2*)&res[(size_t)r0 * N + col];
                    float2 s1 = *(const float2*)&res[(size_t)(r0 + 8) * N + col];
                    o0.x += s0.x; o0.y += s0.y; o1.x += s1.x; o1.y += s1.y;
                }
                if (RELU) {
                    o0.x = fmaxf(o0.x, 0.f); o0.y = fmaxf(o0.y, 0.f);
                    o1.x = fmaxf(o1.x, 0.f); o1.y = fmaxf(o1.y, 0.f);
                }
                *(float2*)&C[(size_t)r0 * N + col] = o0;
                *(float2*)&C[(size_t)(r0 + 8) * N + col] = o1;
            }
        }
    }
}

__global__ void qsum_kernel()
{
    const int b = blockIdx.x, t = threadIdx.x;
    const int s = t & 63, g = t >> 6;
    const float* base = g_tmp + (size_t)b * QKN;
    float sum = 0.f;
    #pragma unroll 4
    for (int m = g; m < NMEM; m += 4) sum += base[m * SQF + s];
    __shared__ float sh[4][64];
    sh[g][s] = sum;
    __syncthreads();
    if (g == 0)
        g_qsum[b * SQF + s] = sh[0][s] + sh[1][s] + sh[2][s] + sh[3][s];
}

__global__ void savg_kernel()
{
    const int b = blockIdx.x, t = threadIdx.x;
    const int lane = t & 31, w = t >> 5;
    __shared__ float q[64];
    if (t < 64) q[t] = g_qsum[b * SQF + t];
    __syncthreads();
    const float* base = g_tmp + (size_t)b * QKN;
    const float inv = 1.0f / (256.0f * 8.0f);
    for (int n = w; n < NMEM; n += 8) {
        float sum = base[n * SQF + lane] * q[lane]
                  + base[n * SQF + 32 + lane] * q[32 + lane];
        #pragma unroll
        for (int off = 16; off; off >>= 1)
            sum += __shfl_xor_sync(0xffffffffu, sum, off);
        if (lane == 0) {
            float val = sum * inv;
            bf16 h = __float2bfloat16(val);
            bf16 l = __float2bfloat16(val - __bfloat162float(h));
            g_savgh[b * NMEM + n] = h;
            g_savgl[b * NMEM + n] = l;
        }
    }
}

extern "C" void kernel_launch(void* const* d_in, const int* in_sizes, int n_in,
                              void* d_out, int out_size)
{
    const float* x  = (const float*)d_in[0];
    const float* Wq = (const float*)d_in[1];
    const float* bq = (const float*)d_in[2];
    const float* Wk = (const float*)d_in[3];
    const float* bk = (const float*)d_in[4];
    const float* v  = (const float*)d_in[5];
    const float* Wl = (const float*)d_in[6];
    const float* bl = (const float*)d_in[7];
    float* out = (float*)d_out;

    float* tmp;
    cudaGetSymbolAddress((void**)&tmp, g_tmp);
    bf16 *wlh,*wll,*vh,*vl,*sh,*sl,*ph,*pl,*xh,*wqh,*wkh;
    cudaGetSymbolAddress((void**)&wlh, g_wlh); cudaGetSymbolAddress((void**)&wll, g_wll);
    cudaGetSymbolAddress((void**)&vh, g_vh);   cudaGetSymbolAddress((void**)&vl, g_vl);
    cudaGetSymbolAddress((void**)&sh, g_savgh);cudaGetSymbolAddress((void**)&sl, g_savgl);
    cudaGetSymbolAddress((void**)&ph, g_ph);   cudaGetSymbolAddress((void**)&pl, g_pl);
    cudaGetSymbolAddress((void**)&xh, g_xh);
    cudaGetSymbolAddress((void**)&wqh, g_wqh); cudaGetSymbolAddress((void**)&wkh, g_wkh);

    // conversions
    conv1_kernel<<<1024, 256>>>((const float4*)x,  (uint2*)xh,  B_SZ * FIN / 4);
    conv1_kernel<<<4096, 256>>>((const float4*)Wq, (uint2*)wqh, FIN * QKN / 4);
    conv1_kernel<<<4096, 256>>>((const float4*)Wk, (uint2*)wkh, FIN * QKN / 4);
    conv_kernel<<<2048, 256>>>((const float4*)Wl, (uint2*)wlh, (uint2*)wll, FIN * FIN / 4);
    conv_kernel<<<512,  256>>>((const float4*)v,  (uint2*)vh,  (uint2*)vl,  NMEM * FIN / 4);

    const int SM = 3 * STAGE_B;
    cudaFuncSetAttribute(tgemm<1, true, true, false, false>,
                         cudaFuncAttributeMaxDynamicSharedMemorySize, SM);
    cudaFuncSetAttribute(tgemm<3, false, false, false, true>,
                         cudaFuncAttributeMaxDynamicSharedMemorySize, SM);
    cudaFuncSetAttribute(tgemm<3, false, true, true, false>,
                         cudaFuncAttributeMaxDynamicSharedMemorySize, SM);

    {   // 1) relu(x@Wq+bq) -> tmp   (single bf16)
        dim3 g(B_SZ / 128, QKN / 128);
        tgemm<1, true, true, false, false><<<g, 256, SM>>>(
            xh, nullptr, wqh, nullptr, bq, nullptr, tmp, nullptr, nullptr,
            B_SZ, QKN, FIN);
    }
    qsum_kernel<<<B_SZ, 256>>>();
    {   // 2) relu(x@Wk+bk) -> tmp   (single bf16)
        dim3 g(B_SZ / 128, QKN / 128);
        tgemm<1, true, true, false, false><<<g, 256, SM>>>(
            xh, nullptr, wkh, nullptr, bk, nullptr, tmp, nullptr, nullptr,
            B_SZ, QKN, FIN);
    }
    savg_kernel<<<B_SZ, 256>>>();
    {   // 3) pooled = s_avg @ v  (split-3, hi/lo out)
        dim3 g(B_SZ / 128, FIN / 128);
        tgemm<3, false, false, false, true><<<g, 256, SM>>>(
            sh, sl, vh, vl, nullptr, nullptr, nullptr, ph, pl, B_SZ, FIN, NMEM);
    }
    {   // 4) out = x + pooled@Wl + bl  (split-3)
        dim3 g(B_SZ / 128, FIN / 128);
        tgemm<3, false, true, true, false><<<g, 256, SM>>>(
            ph, pl, wlh, wll, bl, x, out, nullptr, nullptr, B_SZ, FIN, FIN);
    }
}

// round 10
// speedup vs baseline: 4.2234x; 1.1733x over previous
#include <cuda_runtime.h>
#include <cuda_bf16.h>
#include <cstdint>

#define B_SZ 1024
#define FIN  4096
#define NMEM 256
#define SQF  64
#define QKN  16384
typedef __nv_bfloat16 bf16;

// scratch
__device__ float g_tmp[B_SZ * QKN];                 // relu(xk) fp32
__device__ float g_part[128 * B_SZ * SQF];          // qsum partials per n-tile
__device__ float g_qsum[B_SZ * SQF];
__device__ bf16 g_savgh[B_SZ * NMEM], g_savgl[B_SZ * NMEM];
__device__ bf16 g_v2h[NMEM * FIN], g_v2l[NMEM * FIN];   // V2 = v @ Wl
__device__ bf16 g_vh[NMEM * FIN], g_vl[NMEM * FIN];
__device__ bf16 g_wlh[FIN * FIN], g_wll[FIN * FIN];
__device__ bf16 g_xh[B_SZ * FIN];
__device__ bf16 g_wqh[(size_t)FIN * QKN];
__device__ bf16 g_wkh[(size_t)FIN * QKN];

__device__ __forceinline__ uint32_t smem_u32(const void* p) {
    uint32_t a;
    asm("{ .reg .u64 t; cvta.to.shared.u64 t, %1; cvt.u32.u64 %0, t; }"
        : "=r"(a) : "l"(p));
    return a;
}
__device__ __forceinline__ void ldsm4(uint32_t* r, uint32_t a) {
    asm volatile("ldmatrix.sync.aligned.m8n8.x4.shared.b16 {%0,%1,%2,%3}, [%4];"
                 : "=r"(r[0]), "=r"(r[1]), "=r"(r[2]), "=r"(r[3]) : "r"(a));
}
__device__ __forceinline__ void ldsm4t(uint32_t* r, uint32_t a) {
    asm volatile("ldmatrix.sync.aligned.m8n8.x4.trans.shared.b16 {%0,%1,%2,%3}, [%4];"
                 : "=r"(r[0]), "=r"(r[1]), "=r"(r[2]), "=r"(r[3]) : "r"(a));
}
__device__ __forceinline__ void mma_bf16(float* d, const uint32_t* a, const uint32_t* b) {
    asm volatile(
        "mma.sync.aligned.m16n8k16.row.col.f32.bf16.bf16.f32 "
        "{%0,%1,%2,%3}, {%4,%5,%6,%7}, {%8,%9}, {%0,%1,%2,%3};"
        : "+f"(d[0]), "+f"(d[1]), "+f"(d[2]), "+f"(d[3])
        : "r"(a[0]), "r"(a[1]), "r"(a[2]), "r"(a[3]), "r"(b[0]), "r"(b[1]));
}
__device__ __forceinline__ void cpa16(uint32_t dst, const void* src) {
    asm volatile("cp.async.ca.shared.global [%0], [%1], 16;" :: "r"(dst), "l"(src));
}
__device__ __forceinline__ void cpa_commit() {
    asm volatile("cp.async.commit_group;" ::: "memory");
}
template<int N> __device__ __forceinline__ void cpa_wait() {
    asm volatile("cp.async.wait_group %0;" :: "n"(N) : "memory");
}
__device__ __forceinline__ void split2(float x, float y, uint32_t& hi, uint32_t& lo) {
    bf16 hx = __float2bfloat16(x);
    bf16 hy = __float2bfloat16(y);
    bf16 lx = __float2bfloat16(x - __bfloat162float(hx));
    bf16 ly = __float2bfloat16(y - __bfloat162float(hy));
    hi = (uint32_t)__bfloat16_as_ushort(hx) | ((uint32_t)__bfloat16_as_ushort(hy) << 16);
    lo = (uint32_t)__bfloat16_as_ushort(lx) | ((uint32_t)__bfloat16_as_ushort(ly) << 16);
}

// fp32 -> bf16 hi/lo
__global__ void conv_kernel(const float4* __restrict__ in,
                            uint2* __restrict__ hi, uint2* __restrict__ lo, int n4)
{
    int i = blockIdx.x * blockDim.x + threadIdx.x;
    const int stride = gridDim.x * blockDim.x;
    for (; i < n4; i += stride) {
        float4 v = in[i];
        uint32_t h0, l0, h1, l1;
        split2(v.x, v.y, h0, l0);
        split2(v.z, v.w, h1, l1);
        hi[i] = make_uint2(h0, h1);
        lo[i] = make_uint2(l0, l1);
    }
}
// fp32 -> bf16 (round only)
__global__ void conv1_kernel(const float4* __restrict__ in,
                             uint2* __restrict__ hi, int n4)
{
    int i = blockIdx.x * blockDim.x + threadIdx.x;
    const int stride = gridDim.x * blockDim.x;
    for (; i < n4; i += stride) {
        float4 v = in[i];
        uint32_t h0 = (uint32_t)__bfloat16_as_ushort(__float2bfloat16(v.x))
                    | ((uint32_t)__bfloat16_as_ushort(__float2bfloat16(v.y)) << 16);
        uint32_t h1 = (uint32_t)__bfloat16_as_ushort(__float2bfloat16(v.z))
                    | ((uint32_t)__bfloat16_as_ushort(__float2bfloat16(v.w)) << 16);
        hi[i] = make_uint2(h0, h1);
    }
}

// ---------------------------------------------------------------------------
// bf16 GEMM, TERMS=1 or 3. CTA 128x128, BK=32, 3-stage cp.async.
// EPI: 0 = store C (fp32 or bf16 hi/lo per OUTBF), 1 = qsum-partial fusion.
// ---------------------------------------------------------------------------
#define STAGE_B 32768

template<int TERMS, int EPI, bool RELU, bool BIAS, bool RES, bool OUTBF>
__global__ __launch_bounds__(256)
void tgemm(const bf16* __restrict__ Ah, const bf16* __restrict__ Al,
           const bf16* __restrict__ Bh, const bf16* __restrict__ Bl,
           const float* __restrict__ bias, const float* __restrict__ res,
           float* __restrict__ C, bf16* __restrict__ Ch, bf16* __restrict__ Cl,
           float* __restrict__ part, int M, int N, int K)
{
    extern __shared__ uint8_t smem[];
    const uint32_t sb = smem_u32(smem);
    const int tid = threadIdx.x;
    const int lane = tid & 31, wid = tid >> 5;
    const int wm = wid & 1, wn = wid >> 1;
    const int bm0 = blockIdx.x * 128, bn0 = blockIdx.y * 128;

    const int arow = tid >> 1, ac = (tid & 1) * 32;
    const int brow = tid >> 3, bc = (tid & 7) * 32;
    const bf16* pAh = Ah + (size_t)(bm0 + arow) * K + ac / 2;
    const bf16* pAl = (TERMS == 3) ? Al + (size_t)(bm0 + arow) * K + ac / 2 : nullptr;
    const bf16* pBh = Bh + (size_t)brow * N + bn0 + bc / 2;
    const bf16* pBl = (TERMS == 3) ? Bl + (size_t)brow * N + bn0 + bc / 2 : nullptr;
    const uint32_t aswz = (uint32_t)((arow & 3) << 4);
    const uint32_t bswz = (uint32_t)((brow & 7) << 4);
    const uint32_t ao = (uint32_t)(arow * 64 + ac);
    const uint32_t bo = (uint32_t)(brow * 256 + bc);

    const int NC = K >> 5;

    auto issue = [&](int c) {
        const uint32_t u = sb + (uint32_t)(c % 3) * STAGE_B;
        const bf16* sAh = pAh + c * 32;
        const bf16* sBh = pBh + (size_t)c * 32 * N;
        cpa16(u + ((ao) ^ aswz), sAh);
        cpa16(u + ((ao + 16) ^ aswz), sAh + 8);
        cpa16(u + 16384 + ((bo) ^ bswz), sBh);
        cpa16(u + 16384 + ((bo + 16) ^ bswz), sBh + 8);
        if (TERMS == 3) {
            const bf16* sAl = pAl + c * 32;
            const bf16* sBl = pBl + (size_t)c * 32 * N;
            cpa16(u + 8192 + ((ao) ^ aswz), sAl);
            cpa16(u + 8192 + ((ao + 16) ^ aswz), sAl + 8);
            cpa16(u + 24576 + ((bo) ^ bswz), sBl);
            cpa16(u + 24576 + ((bo + 16) ^ bswz), sBl + 8);
        }
        cpa_commit();
    };

    float acc[16][4];
    #pragma unroll
    for (int i = 0; i < 16; i++)
        #pragma unroll
        for (int j = 0; j < 4; j++) acc[i][j] = 0.f;

    issue(0); issue(1); issue(2);

    for (int c = 0; c < NC; c++) {
        cpa_wait<2>();
        __syncthreads();
        const uint32_t u = sb + (uint32_t)(c % 3) * STAGE_B;
        #pragma unroll
        for (int ks = 0; ks < 2; ks++) {
            uint32_t ah[4][4], al[4][4], bh[2][4], bl[2][4];
            #pragma unroll
            for (int mi = 0; mi < 4; mi++) {
                int row = wm * 64 + mi * 16 + (lane & 15);
                uint32_t ad = (uint32_t)(row * 64 + ks * 32 + (lane >> 4) * 16);
                uint32_t sw = ad ^ ((uint32_t)(row & 3) << 4);
                ldsm4(ah[mi], u + sw);
                if (TERMS == 3) ldsm4(al[mi], u + 8192 + sw);
            }
            #pragma unroll
            for (int j = 0; j < 2; j++) {
                int kk = ks * 16 + (lane & 15);
                int nn = wn * 32 + j * 16 + (lane >> 4) * 8;
                uint32_t bd = (uint32_t)(kk * 256 + nn * 2);
                uint32_t sw = bd ^ ((uint32_t)(kk & 7) << 4);
                ldsm4t(bh[j], u + 16384 + sw);
                if (TERMS == 3) ldsm4t(bl[j], u + 24576 + sw);
            }
            #pragma unroll
            for (int mi = 0; mi < 4; mi++)
                #pragma unroll
                for (int nj = 0; nj < 4; nj++) {
                    const uint32_t* Bh2 = &bh[nj >> 1][(nj & 1) * 2];
                    float* d = acc[mi * 4 + nj];
                    mma_bf16(d, ah[mi], Bh2);
                    if (TERMS == 3) {
                        const uint32_t* Bl2 = &bl[nj >> 1][(nj & 1) * 2];
                        mma_bf16(d, ah[mi], Bl2);
                        mma_bf16(d, al[mi], Bh2);
                    }
                }
        }
        __syncthreads();
        // clamp: keep issuing (dup of last chunk) so wait<2> semantics stay valid
        issue(c + 3 < NC ? c + 3 : NC - 1);
    }
    cpa_wait<0>();
    __syncthreads();

    if (EPI == 1) {
        // fused qsum partials: qs[row][s] = sum over this CTA's 2 slots of relu
        float* qs = (float*)smem;   // 128*64 floats = 32KB (stages are done)
        if (wn < 2) {
            #pragma unroll
            for (int mi = 0; mi < 4; mi++) {
                int r0l = wm * 64 + mi * 16 + (lane >> 2);
                #pragma unroll
                for (int nj = 0; nj < 4; nj++) {
                    int col = wn * 32 + nj * 8 + (lane & 3) * 2;
                    float* d = acc[mi * 4 + nj];
                    float b0 = BIAS ? bias[bn0 + col] : 0.f;
                    float b1 = BIAS ? bias[bn0 + col + 1] : 0.f;
                    qs[r0l * 64 + col]           = fmaxf(d[0] + b0, 0.f);
                    qs[r0l * 64 + col + 1]       = fmaxf(d[1] + b1, 0.f);
                    qs[(r0l + 8) * 64 + col]     = fmaxf(d[2] + b0, 0.f);
                    qs[(r0l + 8) * 64 + col + 1] = fmaxf(d[3] + b1, 0.f);
                }
            }
        }
        __syncthreads();
        if (wn >= 2) {
            #pragma unroll
            for (int mi = 0; mi < 4; mi++) {
                int r0l = wm * 64 + mi * 16 + (lane >> 2);
                #pragma unroll
                for (int nj = 0; nj < 4; nj++) {
                    int col = wn * 32 + nj * 8 + (lane & 3) * 2;
                    float* d = acc[mi * 4 + nj];
                    float b0 = BIAS ? bias[bn0 + col] : 0.f;
                    float b1 = BIAS ? bias[bn0 + col + 1] : 0.f;
                    qs[r0l * 64 + col - 64]           += fmaxf(d[0] + b0, 0.f);
                    qs[r0l * 64 + col - 63]           += fmaxf(d[1] + b1, 0.f);
                    qs[(r0l + 8) * 64 + col - 64]     += fmaxf(d[2] + b0, 0.f);
                    qs[(r0l + 8) * 64 + col - 63]     += fmaxf(d[3] + b1, 0.f);
                }
            }
        }
        __syncthreads();
        for (int i = tid; i < 8192; i += 256)
            part[(size_t)blockIdx.y * (B_SZ * SQF) + bm0 * 64 + i] = qs[i];
        return;
    }

    #pragma unroll
    for (int mi = 0; mi < 4; mi++) {
        const int r0 = bm0 + wm * 64 + mi * 16 + (lane >> 2);
        #pragma unroll
        for (int nj = 0; nj < 4; nj++) {
            const int col = bn0 + wn * 32 + nj * 8 + (lane & 3) * 2;
            float* d = acc[mi * 4 + nj];
            if (OUTBF) {
                #pragma unroll
                for (int h = 0; h < 2; h++) {
                    const int rr = r0 + 8 * h;
                    uint32_t hi, lo;
                    split2(d[2 * h], d[2 * h + 1], hi, lo);
                    *(uint32_t*)&Ch[(size_t)rr * N + col] = hi;
                    *(uint32_t*)&Cl[(size_t)rr * N + col] = lo;
                }
            } else {
                float2 o0 = make_float2(d[0], d[1]);
                float2 o1 = make_float2(d[2], d[3]);
                if (BIAS) {
                    float2 bb = *(const float2*)&bias[col];
                    o0.x += bb.x; o0.y += bb.y; o1.x += bb.x; o1.y += bb.y;
                }
                if (RES) {
                    float2 s0 = *(const float2*)&res[(size_t)r0 * N + col];
                    float2 s1 = *(const float2*)&res[(size_t)(r0 + 8) * N + col];
                    o0.x += s0.x; o0.y += s0.y; o1.x += s1.x; o1.y += s1.y;
                }
                if (RELU) {
                    o0.x = fmaxf(o0.x, 0.f); o0.y = fmaxf(o0.y, 0.f);
                    o1.x = fmaxf(o1.x, 0.f); o1.y = fmaxf(o1.y, 0.f);
                }
                *(float2*)&C[(size_t)r0 * N + col] = o0;
                *(float2*)&C[(size_t)(r0 + 8) * N + col] = o1;
            }
        }
    }
}

// qsum[b,s] = sum over 128 n-tiles of partials
__global__ void qsum_reduce()
{
    const int idx = blockIdx.x * 256 + threadIdx.x;   // < 65536
    float s = 0.f;
    #pragma unroll 8
    for (int nt = 0; nt < 128; nt++) s += g_part[(size_t)nt * (B_SZ * SQF) + idx];
    g_qsum[idx] = s;
}

// s_avg[b,n] = (1/2048) sum_s xk[b,n*64+s] * qsum[b,s]   -> bf16 hi/lo
__global__ void savg_kernel()
{
    const int b = blockIdx.x, t = threadIdx.x;
    const int lane = t & 31, w = t >> 5;
    __shared__ float q[64];
    if (t < 64) q[t] = g_qsum[b * SQF + t];
    __syncthreads();
    const float* base = g_tmp + (size_t)b * QKN;
    const float inv = 1.0f / 2048.0f;
    for (int n = w; n < NMEM; n += 8) {
        float sum = base[n * SQF + lane] * q[lane]
                  + base[n * SQF + 32 + lane] * q[32 + lane];
        #pragma unroll
        for (int off = 16; off; off >>= 1)
            sum += __shfl_xor_sync(0xffffffffu, sum, off);
        if (lane == 0) {
            float val = sum * inv;
            bf16 h = __float2bfloat16(val);
            bf16 l = __float2bfloat16(val - __bfloat162float(h));
            g_savgh[b * NMEM + n] = h;
            g_savgl[b * NMEM + n] = l;
        }
    }
}

extern "C" void kernel_launch(void* const* d_in, const int* in_sizes, int n_in,
                              void* d_out, int out_size)
{
    const float* x  = (const float*)d_in[0];
    const float* Wq = (const float*)d_in[1];
    const float* bq = (const float*)d_in[2];
    const float* Wk = (const float*)d_in[3];
    const float* bk = (const float*)d_in[4];
    const float* v  = (const float*)d_in[5];
    const float* Wl = (const float*)d_in[6];
    const float* bl = (const float*)d_in[7];
    float* out = (float*)d_out;

    float *tmp, *partp;
    cudaGetSymbolAddress((void**)&tmp, g_tmp);
    cudaGetSymbolAddress((void**)&partp, g_part);
    bf16 *wlh,*wll,*vh,*vl,*sh,*sl,*v2h,*v2l,*xh,*wqh,*wkh;
    cudaGetSymbolAddress((void**)&wlh, g_wlh); cudaGetSymbolAddress((void**)&wll, g_wll);
    cudaGetSymbolAddress((void**)&vh, g_vh);   cudaGetSymbolAddress((void**)&vl, g_vl);
    cudaGetSymbolAddress((void**)&sh, g_savgh);cudaGetSymbolAddress((void**)&sl, g_savgl);
    cudaGetSymbolAddress((void**)&v2h, g_v2h); cudaGetSymbolAddress((void**)&v2l, g_v2l);
    cudaGetSymbolAddress((void**)&xh, g_xh);
    cudaGetSymbolAddress((void**)&wqh, g_wqh); cudaGetSymbolAddress((void**)&wkh, g_wkh);

    const int SM = 3 * STAGE_B;
    cudaFuncSetAttribute(tgemm<1, 1, true, true, false, false>,
                         cudaFuncAttributeMaxDynamicSharedMemorySize, SM);
    cudaFuncSetAttribute(tgemm<1, 0, true, true, false, false>,
                         cudaFuncAttributeMaxDynamicSharedMemorySize, SM);
    cudaFuncSetAttribute(tgemm<3, 0, false, false, false, true>,
                         cudaFuncAttributeMaxDynamicSharedMemorySize, SM);
    cudaFuncSetAttribute(tgemm<3, 0, false, true, true, false>,
                         cudaFuncAttributeMaxDynamicSharedMemorySize, SM);

    // ---- single stream, graph-capturable, allocation-free ----

    // x conversion
    conv1_kernel<<<1024, 256>>>((const float4*)x, (uint2*)xh, B_SZ * FIN / 4);

    // Q branch: conv Wq, GEMM1 with fused qsum partials, reduce
    conv1_kernel<<<4096, 256>>>((const float4*)Wq, (uint2*)wqh, FIN * QKN / 4);
    {
        dim3 g(B_SZ / 128, QKN / 128);
        tgemm<1, 1, true, true, false, false><<<g, 256, SM>>>(
            xh, nullptr, wqh, nullptr, bq, nullptr, nullptr, nullptr, nullptr,
            partp, B_SZ, QKN, FIN);
    }
    qsum_reduce<<<256, 256>>>();

    // K branch: conv Wk, GEMM2 -> relu(xk) fp32
    conv1_kernel<<<4096, 256>>>((const float4*)Wk, (uint2*)wkh, FIN * QKN / 4);
    {
        dim3 g(B_SZ / 128, QKN / 128);
        tgemm<1, 0, true, true, false, false><<<g, 256, SM>>>(
            xh, nullptr, wkh, nullptr, bk, nullptr, tmp, nullptr, nullptr, nullptr,
            B_SZ, QKN, FIN);
    }
    savg_kernel<<<B_SZ, 256>>>();

    // V2 = v @ Wl (split-3, bf16 hi/lo out)
    conv_kernel<<<2048, 256>>>((const float4*)Wl, (uint2*)wlh, (uint2*)wll,
                               FIN * FIN / 4);
    conv_kernel<<<512, 256>>>((const float4*)v, (uint2*)vh, (uint2*)vl,
                              NMEM * FIN / 4);
    {
        dim3 g(NMEM / 128, FIN / 128);
        tgemm<3, 0, false, false, false, true><<<g, 256, SM>>>(
            vh, vl, wlh, wll, nullptr, nullptr, nullptr, v2h, v2l, nullptr,
            NMEM, FIN, FIN);
    }

    // out = x + s_avg @ V2 + bl   (K = 256)
    {
        dim3 g(B_SZ / 128, FIN / 128);
        tgemm<3, 0, false, true, true, false><<<g, 256, SM>>>(
            sh, sl, v2h, v2l, bl, x, out, nullptr, nullptr, nullptr,
            B_SZ, FIN, NMEM);
    }
}